// round 16
// baseline (speedup 1.0000x reference)
#include <cuda_runtime.h>

// RecursiveFilter: y[0]=x[0]; y[n] = W*x[n] + (1-W)*y[n-1] along axis 2 (N)
// Shape: [B=4, C=3, N=32, H=256, W=256] fp32, contiguous.
// One thread per float4 lane of (h,w). Recurrence serial only along N=32.
//
// FINAL (best measured: 27.81us kernel, 5.51 TB/s DRAM, 69.6% of spec,
// harness 35.33us):
//  - 768 CTAs x 256 threads, one thread per float4 lane, single wave
//  - loads default policy, stores write-through (__stwt): output never
//    allocates in L2, keeps replacement pressure off the read stream
//  - 4-frame load batches ahead of the carry chain (MLP_p1 = 4)
// Traffic is algorithmically minimal (201.3 MB goodput); combined LTS
// goodput ~7.2 TB/s sits at the measured path-independent chip LTS cap,
// and DRAM sits at the read/write-interleave ceiling -> hardware floor.
// Falsified levers: CTA balance (768/1536/3072), MLP=8, __ldcs/__stcs,
// L2::evict_last cross-replay pinning, 32B loads (kills occupancy +
// within-LDG L1tex replays). Plateau noise band: 27.8-29.3us kernel.

#define FW 0.3f
#define FW1 0.7f

static constexpr int Ndim = 32;
static constexpr int HW   = 256 * 256;   // elements per frame per (b,c)
static constexpr int HW4  = HW / 4;      // 16384 float4 per frame
static constexpr int BC   = 4 * 3;
static constexpr int TPB  = 256;

__device__ __forceinline__ float4 ema4(float4 v, float4 c) {
    float4 r;
    r.x = FW * v.x + FW1 * c.x;
    r.y = FW * v.y + FW1 * c.y;
    r.z = FW * v.z + FW1 * c.z;
    r.w = FW * v.w + FW1 * c.w;
    return r;
}

__global__ __launch_bounds__(TPB)
void recursive_filter_kernel(const float4* __restrict__ x,
                             float4* __restrict__ y)
{
    int hw4 = blockIdx.x * TPB + threadIdx.x;   // 0..HW4-1 (exact)
    int bc  = blockIdx.y;                       // 0..BC-1

    const float4* xp = x + (long)bc * Ndim * HW4 + hw4;
    float4*       yp = y + (long)bc * Ndim * HW4 + hw4;

    float4 c;

    // chunk 0: frames 0..3 (frame 0 is identity)
    {
        float4 v0 = xp[0 * HW4];
        float4 v1 = xp[1 * HW4];
        float4 v2 = xp[2 * HW4];
        float4 v3 = xp[3 * HW4];
        c = v0;            __stwt(yp + 0 * HW4, c);
        c = ema4(v1, c);   __stwt(yp + 1 * HW4, c);
        c = ema4(v2, c);   __stwt(yp + 2 * HW4, c);
        c = ema4(v3, c);   __stwt(yp + 3 * HW4, c);
    }

    // chunks 1..7: frames 4..31
#pragma unroll
    for (int n0 = 4; n0 < Ndim; n0 += 4) {
        float4 v0 = xp[(n0 + 0) * HW4];
        float4 v1 = xp[(n0 + 1) * HW4];
        float4 v2 = xp[(n0 + 2) * HW4];
        float4 v3 = xp[(n0 + 3) * HW4];
        c = ema4(v0, c);   __stwt(yp + (n0 + 0) * HW4, c);
        c = ema4(v1, c);   __stwt(yp + (n0 + 1) * HW4, c);
        c = ema4(v2, c);   __stwt(yp + (n0 + 2) * HW4, c);
        c = ema4(v3, c);   __stwt(yp + (n0 + 3) * HW4, c);
    }
}

extern "C" void kernel_launch(void* const* d_in, const int* in_sizes, int n_in,
                              void* d_out, int out_size)
{
    const float4* x = (const float4*)d_in[0];
    float4* y = (float4*)d_out;

    dim3 grid(HW4 / TPB, BC, 1);   // (64, 12) = 768 CTAs of 256 threads
    recursive_filter_kernel<<<grid, TPB>>>(x, y);
}